// round 16
// baseline (speedup 1.0000x reference)
#include <cuda_runtime.h>
#include <cuda_bf16.h>
#include <cstdint>
#include <cstddef>

using bf16 = __nv_bfloat16;

constexpr int BATCH  = 2;
constexpr int CDIM   = 192;
constexpr int HH     = 256;
constexpr int WW     = 256;
constexpr int PIX    = HH * WW;          // 65536
constexpr int NHEADS = 4;
constexpr int HD     = 48;               // CDIM / NHEADS
constexpr int HID    = 510;
constexpr int QKVC   = 3 * CDIM;         // 576
constexpr int FFNC   = 2 * HID;          // 1020
constexpr int FFNCP  = 1024;             // padded ffn channels

// ----------------------------- device scratch -------------------------------
__device__ float d_mu2[BATCH * PIX];
__device__ float d_rs2[BATCH * PIX];
__device__ bf16  d_qkv  [(size_t)BATCH * QKVC * PIX];     // conv1x1(qkv), bf16
__device__ float d_x1   [(size_t)BATCH * CDIM * PIX];     // x + attn branch
__device__ bf16  d_h    [(size_t)BATCH * FFNCP * PIX];    // ffn_in conv1x1 (padded)
__device__ float d_G   [BATCH * NHEADS * HD * HD];
__device__ float d_qn  [BATCH * NHEADS * HD];
__device__ float d_kn  [BATCH * NHEADS * HD];
__device__ float d_attn[BATCH * NHEADS * HD * HD];
// pre-converted bf16 weights
__device__ bf16  d_wq [QKVC * CDIM];          // qkv_w
__device__ bf16  d_w2 [FFNCP * CDIM];         // ffn_in_w, rows 1020..1023 zero
__device__ bf16  d_w3 [CDIM * 512];           // ffn_out_w, cols 510,511 zero
__device__ bf16  d_Mh [BATCH * CDIM * CDIM];  // proj_w @ blockdiag(attn)

// ----------------------------- helpers --------------------------------------
__device__ __forceinline__ float ldbf(const bf16* p)
{
    unsigned short u = __ldg(reinterpret_cast<const unsigned short*>(p));
    __nv_bfloat16_raw r; r.x = u;
    return __bfloat162float(bf16(r));
}

__device__ __forceinline__ void unpack8(uint4 u, float* f)
{
    unsigned v[4] = {u.x, u.y, u.z, u.w};
#pragma unroll
    for (int i = 0; i < 4; ++i) {
        __nv_bfloat162 h = *reinterpret_cast<__nv_bfloat162*>(&v[i]);
        f[i * 2]     = __low2float(h);
        f[i * 2 + 1] = __high2float(h);
    }
}

__device__ __forceinline__ void store16(bf16* dst, const float* f)
{
    uint4 u[2];
    unsigned* p = reinterpret_cast<unsigned*>(u);
#pragma unroll
    for (int i = 0; i < 8; ++i) {
        __nv_bfloat162 h(__float2bfloat16(f[i * 2]), __float2bfloat16(f[i * 2 + 1]));
        p[i] = *reinterpret_cast<unsigned*>(&h);
    }
    reinterpret_cast<uint4*>(dst)[0] = u[0];
    reinterpret_cast<uint4*>(dst)[1] = u[1];
}

__device__ __forceinline__ void ldsm4(unsigned& r0, unsigned& r1, unsigned& r2,
                                      unsigned& r3, const void* p)
{
    unsigned a = (unsigned)__cvta_generic_to_shared(p);
    asm volatile("ldmatrix.sync.aligned.m8n8.x4.shared.b16 {%0,%1,%2,%3}, [%4];"
                 : "=r"(r0), "=r"(r1), "=r"(r2), "=r"(r3) : "r"(a));
}
__device__ __forceinline__ void ldsm4t(unsigned& r0, unsigned& r1, unsigned& r2,
                                       unsigned& r3, const void* p)
{
    unsigned a = (unsigned)__cvta_generic_to_shared(p);
    asm volatile("ldmatrix.sync.aligned.m8n8.x4.trans.shared.b16 {%0,%1,%2,%3}, [%4];"
                 : "=r"(r0), "=r"(r1), "=r"(r2), "=r"(r3) : "r"(a));
}
__device__ __forceinline__ void mma16816(float (&d)[4], const unsigned (&a)[4],
                                         unsigned b0, unsigned b1)
{
    asm volatile(
        "mma.sync.aligned.m16n8k16.row.col.f32.bf16.bf16.f32 "
        "{%0,%1,%2,%3},{%4,%5,%6,%7},{%8,%9},{%0,%1,%2,%3};"
        : "+f"(d[0]), "+f"(d[1]), "+f"(d[2]), "+f"(d[3])
        : "r"(a[0]), "r"(a[1]), "r"(a[2]), "r"(a[3]), "r"(b0), "r"(b1));
}
__device__ __forceinline__ void cpasync16(void* dst, const void* src)
{
    unsigned d = (unsigned)__cvta_generic_to_shared(dst);
    asm volatile("cp.async.ca.shared.global [%0], [%1], 16;" :: "r"(d), "l"(src));
}
__device__ __forceinline__ void cp_commit()
{
    asm volatile("cp.async.commit_group;");
}
__device__ __forceinline__ void cp_wait0()
{
    asm volatile("cp.async.wait_group 0;");
}

// --------------- weight pre-conversion to bf16 + stats zeroing ---------------
__global__ __launch_bounds__(256) void prep_w_kernel(
    const float* __restrict__ qkv_w,
    const float* __restrict__ ffn_in_w,
    const float* __restrict__ ffn_out_w)
{
    int i = blockIdx.x * 256 + threadIdx.x;    // up to FFNCP*CDIM = 196608
    if (i < QKVC * CDIM)
        d_wq[i] = __float2bfloat16(__ldg(&qkv_w[i]));
    if (i < FFNCP * CDIM) {
        int r = i / CDIM;
        d_w2[i] = (r < FFNC) ? __float2bfloat16(__ldg(&ffn_in_w[i]))
                             : __float2bfloat16(0.f);
    }
    if (i < CDIM * 512) {
        int r = i >> 9, c = i & 511;
        d_w3[i] = (c < HID) ? __float2bfloat16(__ldg(&ffn_out_w[r * HID + c]))
                            : __float2bfloat16(0.f);
    }
    if (i < BATCH * NHEADS * HD * HD) d_G[i] = 0.f;
    if (i < BATCH * NHEADS * HD) { d_qn[i] = 0.f; d_kn[i] = 0.f; }
}

// ----------------------------- tensor-core GEMM (modes 0..2) ----------------
// out[b,o,p] = sum_k A[o,k]*B[b,k,p] ; A in bf16 (pre-converted, KP-strided).
// MODE 0: A=d_wq [576x192], B=LN1(x) (stats fused!) -> d_qkv (bf16)
// MODE 1: A=d_Mh [192x192], B=dw3x3(V) fused        -> d_x1, + LN2 stats
// MODE 2: A=d_w2 [1024x192],B=LN2(x1)               -> d_h (bf16)
template <int MODE>
__global__ __launch_bounds__(256) void gemm_mma(
    const float* __restrict__ Barg,     // MODE0: x
    const float* __restrict__ lnw,      // MODE0/2: ln weight; MODE1: dw-conv weights
    const float* __restrict__ lnb,
    const float* __restrict__ resArg,   // MODE1: x
    float* __restrict__ outArg)
{
    constexpr int  O   = (MODE == 0) ? QKVC : (MODE == 2) ? FFNCP : CDIM;
    constexpr int  KP  = 192;
    constexpr int  BN  = 128;
    constexpr int  BNP = BN + 8;
    constexpr int  KAP = KP + 8;
    constexpr int  MT  = O / 64;
    constexpr int  WN  = BN / 4;
    constexpr int  WNF = WN / 8;
    constexpr int  NP  = WNF / 2;
    constexpr int  ACH = KP / 8;          // 16B chunks per A row

    extern __shared__ __align__(16) char smem_raw[];
    bf16* Bs  = reinterpret_cast<bf16*>(smem_raw);                       // [KP][BNP]
    bf16* As0 = reinterpret_cast<bf16*>(smem_raw + KP * BNP * 2);        // 2x [64][KAP]
    bf16* Asb[2] = {As0, As0 + 64 * KAP};
    float* fdyn = reinterpret_cast<float*>(smem_raw + KP * BNP * 2 + 2 * 64 * KAP * 2);
    float* mu_s  = fdyn;                 // [BN]
    float* rs_s  = fdyn + BN;            // [BN]
    float* lnw_s = fdyn + 2 * BN;        // [KP]
    float* lnb_s = fdyn + 2 * BN + KP;   // [KP]
    float* s_cs  = fdyn + 2 * BN + 2 * KP;        // MODE0 col sums [BN]
    float* s_cq  = fdyn + 2 * BN + 2 * KP + BN;   // MODE0 col sq-sums [BN]
    float* m1_cs = fdyn;                 // MODE1 aliases
    float* m1_cq = fdyn + BN;

    const int b    = blockIdx.y;
    const int n0   = blockIdx.x * BN;
    const int tid  = threadIdx.x;
    const int lane = tid & 31;
    const int warp = tid >> 5;
    const int wm   = (warp >> 2) * 32;   // 0 or 32
    const int wn   = (warp & 3) * WN;

    // per-mode pointers
    const bf16* Ab;
    const float* Bf = nullptr;
    const float* resb = nullptr;
    bf16*  out16 = nullptr;     float* out32 = nullptr;
    if constexpr (MODE == 0) {
        Ab = d_wq;  Bf = Barg + (size_t)b * CDIM * PIX;
        out16 = d_qkv + (size_t)b * QKVC * PIX;
    } else if constexpr (MODE == 1) {
        Ab = d_Mh + (size_t)b * CDIM * CDIM;
        resb = resArg + (size_t)b * CDIM * PIX;               // x
        out32 = d_x1 + (size_t)b * CDIM * PIX;
    } else {
        Ab = d_w2;  Bf = d_x1 + (size_t)b * CDIM * PIX;
        out16 = d_h + (size_t)b * FFNCP * PIX;
    }

    // ---- kick off A tile 0 prefetch ----
    {
        const bf16* src = Ab;
        for (int c = tid; c < 64 * ACH; c += 256) {
            int row = c / ACH, ch = c % ACH;
            cpasync16(&Asb[0][row * KAP + ch * 8], src + row * KP + ch * 8);
        }
        cp_commit();
    }

    // ---- B tile fill MODE0: raw x -> bf16, LN1 stats fused, normalize ----
    if constexpr (MODE == 0) {
        if (tid < BN) { s_cs[tid] = 0.f; s_cq[tid] = 0.f; }
        for (int i = tid; i < KP; i += 256) {
            lnw_s[i] = __ldg(&lnw[i]);
            lnb_s[i] = __ldg(&lnb[i]);
        }
        __syncthreads();
        const int c = (tid & 63) * 2;   // fixed column pair per thread
        float cs0 = 0.f, cq0 = 0.f, cs1 = 0.f, cq1 = 0.f;
        for (int e = tid; e < KP * BN / 2; e += 256) {
            int k = e >> 6;
            float2 xv = *reinterpret_cast<const float2*>(&Bf[(size_t)k * PIX + n0 + c]);
            cs0 += xv.x; cq0 = fmaf(xv.x, xv.x, cq0);
            cs1 += xv.y; cq1 = fmaf(xv.y, xv.y, cq1);
            __nv_bfloat162 hh(__float2bfloat16(xv.x), __float2bfloat16(xv.y));
            *reinterpret_cast<__nv_bfloat162*>(&Bs[k * BNP + c]) = hh;
        }
        atomicAdd(&s_cs[c],     cs0); atomicAdd(&s_cq[c],     cq0);
        atomicAdd(&s_cs[c + 1], cs1); atomicAdd(&s_cq[c + 1], cq1);
        __syncthreads();
        if (tid < BN) {
            float mu  = s_cs[tid] * (1.f / CDIM);
            float var = fmaxf(s_cq[tid] * (1.f / CDIM) - mu * mu, 0.f);
            mu_s[tid] = mu;
            rs_s[tid] = rsqrtf(var + 1e-5f);
        }
        __syncthreads();
        for (int e = tid; e < KP * BN / 2; e += 256) {
            int k = e >> 6;
            __nv_bfloat162 hh = *reinterpret_cast<__nv_bfloat162*>(&Bs[k * BNP + c]);
            float v0 = (__low2float(hh)  - mu_s[c])     * rs_s[c]     * lnw_s[k] + lnb_s[k];
            float v1 = (__high2float(hh) - mu_s[c + 1]) * rs_s[c + 1] * lnw_s[k] + lnb_s[k];
            *reinterpret_cast<__nv_bfloat162*>(&Bs[k * BNP + c]) =
                __nv_bfloat162(__float2bfloat16(v0), __float2bfloat16(v1));
        }
    }

    // ---- B tile fill MODE2: LN2(x1) using precomputed stats ----
    if constexpr (MODE == 2) {
        for (int i = tid; i < BN; i += 256) {
            mu_s[i] = d_mu2[b * PIX + n0 + i];
            rs_s[i] = d_rs2[b * PIX + n0 + i];
        }
        for (int i = tid; i < KP; i += 256) {
            lnw_s[i] = __ldg(&lnw[i]);
            lnb_s[i] = __ldg(&lnb[i]);
        }
        __syncthreads();
        for (int e = tid; e < KP * BN / 2; e += 256) {
            int k = e >> 6;
            int c = (e & 63) * 2;
            float2 xv = *reinterpret_cast<const float2*>(&Bf[(size_t)k * PIX + n0 + c]);
            float v0 = (xv.x - mu_s[c])     * rs_s[c]     * lnw_s[k] + lnb_s[k];
            float v1 = (xv.y - mu_s[c + 1]) * rs_s[c + 1] * lnw_s[k] + lnb_s[k];
            __nv_bfloat162 h(__float2bfloat16(v0), __float2bfloat16(v1));
            *reinterpret_cast<__nv_bfloat162*>(&Bs[k * BNP + c]) = h;
        }
    }

    if constexpr (MODE == 1) {
        if (tid < BN) { m1_cs[tid] = 0.f; m1_cq[tid] = 0.f; }
    }

    // ---- B tile fill MODE1: dw3x3 of V computed on the fly ----
    if constexpr (MODE == 1) {
        const bf16* Vb = d_qkv + ((size_t)b * QKVC + 2 * CDIM) * PIX;
        const int y  = n0 >> 8;
        const int xs = n0 & 255;
        for (int t = tid; t < CDIM * 8; t += 256) {
            int k  = t >> 3;
            int xb = xs + (t & 7) * 16;
            const float* wp = lnw + (size_t)(2 * CDIM + k) * 9;   // qkv_dw_w
            float wv[9];
#pragma unroll
            for (int i = 0; i < 9; ++i) wv[i] = __ldg(wp + i);
            float out[16];
#pragma unroll
            for (int i = 0; i < 16; ++i) out[i] = 0.f;
            const bf16* chp = Vb + (size_t)k * PIX;
#pragma unroll
            for (int r = 0; r < 3; ++r) {
                int yy = y + r - 1;
                if (yy < 0 || yy >= HH) continue;
                const bf16* rp = chp + yy * WW;
                float rv[18];
                rv[0] = (xb > 0) ? ldbf(rp + xb - 1) : 0.f;
                unpack8(*reinterpret_cast<const uint4*>(rp + xb), rv + 1);
                unpack8(*reinterpret_cast<const uint4*>(rp + xb + 8), rv + 9);
                rv[17] = (xb + 16 < WW) ? ldbf(rp + xb + 16) : 0.f;
                float w0 = wv[r * 3], w1 = wv[r * 3 + 1], w2 = wv[r * 3 + 2];
#pragma unroll
                for (int i = 0; i < 16; ++i)
                    out[i] += w0 * rv[i] + w1 * rv[i + 1] + w2 * rv[i + 2];
            }
            store16(&Bs[k * BNP + (t & 7) * 16], out);
        }
    }

    const int gg = lane >> 2;
    const int t2 = (lane & 3) * 2;

    float cs[8], cq[8];
    if constexpr (MODE == 1) {
#pragma unroll
        for (int j = 0; j < 8; ++j) { cs[j] = 0.f; cq[j] = 0.f; }
    }

    // ---- main loop over output-channel tiles (double-buffered A) ----
    for (int mt = 0; mt < MT; ++mt) {
        cp_wait0();
        __syncthreads();
        if (mt + 1 < MT) {
            const bf16* src = Ab + (size_t)(mt + 1) * 64 * KP;
            bf16* dst = Asb[(mt + 1) & 1];
            for (int c = tid; c < 64 * ACH; c += 256) {
                int row = c / ACH, ch = c % ACH;
                cpasync16(&dst[row * KAP + ch * 8], src + row * KP + ch * 8);
            }
            cp_commit();
        }
        const bf16* Ac = Asb[mt & 1];
        const int m0 = mt * 64;

        float acc[2][WNF][4];
#pragma unroll
        for (int mi = 0; mi < 2; ++mi)
#pragma unroll
            for (int j = 0; j < WNF; ++j)
#pragma unroll
                for (int q = 0; q < 4; ++q) acc[mi][j][q] = 0.f;

#pragma unroll 4
        for (int ks = 0; ks < KP / 16; ++ks) {
            unsigned a[2][4];
#pragma unroll
            for (int mi = 0; mi < 2; ++mi) {
                int row = wm + mi * 16 + (lane & 15);
                int col = ks * 16 + ((lane >> 4) << 3);
                ldsm4(a[mi][0], a[mi][1], a[mi][2], a[mi][3], &Ac[row * KAP + col]);
            }
            unsigned bq[NP][4];
#pragma unroll
            for (int p = 0; p < NP; ++p) {
                int row = ks * 16 + ((lane >> 3) & 1) * 8 + (lane & 7);
                int col = wn + p * 16 + ((lane >> 4) << 3);
                ldsm4t(bq[p][0], bq[p][1], bq[p][2], bq[p][3], &Bs[row * BNP + col]);
            }
#pragma unroll
            for (int mi = 0; mi < 2; ++mi)
#pragma unroll
                for (int j = 0; j < WNF; ++j) {
                    int p = j >> 1;
                    if ((j & 1) == 0) mma16816(acc[mi][j], a[mi], bq[p][0], bq[p][1]);
                    else              mma16816(acc[mi][j], a[mi], bq[p][2], bq[p][3]);
                }
        }

        // ---- store ----
#pragma unroll
        for (int mi = 0; mi < 2; ++mi)
#pragma unroll
            for (int j = 0; j < WNF; ++j) {
                int obase = m0 + wm + mi * 16 + gg;
                int col   = n0 + wn + j * 8 + t2;
#pragma unroll
                for (int half = 0; half < 2; ++half) {
                    int o = obase + half * 8;
                    float v0 = acc[mi][j][half * 2 + 0];
                    float v1 = acc[mi][j][half * 2 + 1];
                    size_t off = (size_t)o * PIX + col;
                    if constexpr (MODE == 0 || MODE == 2) {
                        __nv_bfloat162 pk(__float2bfloat16(v0), __float2bfloat16(v1));
                        *reinterpret_cast<__nv_bfloat162*>(&out16[off]) = pk;
                    } else {
                        float2 rv2 = *reinterpret_cast<const float2*>(&resb[off]);
                        float o0 = v0 + rv2.x;
                        float o1 = v1 + rv2.y;
                        *reinterpret_cast<float2*>(&out32[off]) = make_float2(o0, o1);
                        cs[j * 2]     += o0; cq[j * 2]     += o0 * o0;
                        cs[j * 2 + 1] += o1; cq[j * 2 + 1] += o1 * o1;
                    }
                }
            }
    }

    // ---- MODE1 epilogue: LN2 statistics ----
    if constexpr (MODE == 1) {
#pragma unroll
        for (int s = 0; s < 8; ++s) {
#pragma unroll
            for (int off = 4; off < 32; off <<= 1) {
                cs[s] += __shfl_xor_sync(0xffffffffu, cs[s], off);
                cq[s] += __shfl_xor_sync(0xffffffffu, cq[s], off);
            }
        }
        if (gg == 0) {
#pragma unroll
            for (int s = 0; s < 8; ++s) {
                int c = wn + (s >> 1) * 8 + t2 + (s & 1);
                atomicAdd(&m1_cs[c], cs[s]);
                atomicAdd(&m1_cq[c], cq[s]);
            }
        }
        __syncthreads();
        if (tid < BN) {
            float mu  = m1_cs[tid] * (1.f / CDIM);
            float var = fmaxf(m1_cq[tid] * (1.f / CDIM) - mu * mu, 0.f);
            d_mu2[b * PIX + n0 + tid] = mu;
            d_rs2[b * PIX + n0 + tid] = rsqrtf(var + 1e-5f);
        }
    }
}

// ------------------- gemm3: out = x1 + ffn_out_w @ gate(dw(h)) ---------------
constexpr int KC3  = 256;
constexpr int BNP3 = 72;
constexpr int KAP3 = 264;

__global__ __launch_bounds__(256, 2) void gemm3_kernel(
    const float* __restrict__ dww,      // ffn_dw_w
    float* __restrict__ outArg)
{
    extern __shared__ __align__(16) char smem_raw[];
    bf16* Bs  = reinterpret_cast<bf16*>(smem_raw);                       // [256][72]
    bf16* As0 = reinterpret_cast<bf16*>(smem_raw + KC3 * BNP3 * 2);      // 2x [64][264]
    bf16* Asb[2] = {As0, As0 + 64 * KAP3};

    const int b    = blockIdx.y;
    const int n0   = blockIdx.x * 64;
    const int tid  = threadIdx.x;
    const int lane = tid & 31;
    const int warp = tid >> 5;
    const int wm   = (warp >> 2) * 32;
    const int wn   = (warp & 3) * 16;

    const bf16*  Hb   = d_h + (size_t)b * FFNCP * PIX;
    const float* resb = d_x1 + (size_t)b * CDIM * PIX;
    float* out32      = outArg + (size_t)b * CDIM * PIX;

    // prefetch A tile (kc=0, mt=0)
    for (int c = tid; c < 64 * 32; c += 256) {
        int row = c >> 5, ch = c & 31;
        cpasync16(&Asb[0][row * KAP3 + ch * 8], d_w3 + row * 512 + ch * 8);
    }
    cp_commit();

    float acc[3][2][2][4];
#pragma unroll
    for (int mt = 0; mt < 3; ++mt)
#pragma unroll
        for (int mi = 0; mi < 2; ++mi)
#pragma unroll
            for (int j = 0; j < 2; ++j)
#pragma unroll
                for (int q = 0; q < 4; ++q) acc[mt][mi][j][q] = 0.f;

    const int y  = n0 >> 8;
    const int xs = n0 & 255;

    int pf = 1;     // next A tile in sequence (kc*3 + mt)
    for (int kc = 0; kc < 2; ++kc) {
        if (kc) __syncthreads();    // all mma reads of previous Bs done
        const int kbase = kc * 256;
        const int nch   = (kc == 0) ? 256 : 254;
        for (int t = tid; t < nch * 4; t += 256) {
            int kl = t >> 2;
            int k  = kbase + kl;
            int xb = xs + (t & 3) * 16;
            float s1[16], out[16];
            {
                const float* wp = dww + (size_t)k * 9;
                float wv[9];
#pragma unroll
                for (int i = 0; i < 9; ++i) wv[i] = __ldg(wp + i);
#pragma unroll
                for (int i = 0; i < 16; ++i) s1[i] = 0.f;
                const bf16* chp = Hb + (size_t)k * PIX;
#pragma unroll
                for (int r = 0; r < 3; ++r) {
                    int yy = y + r - 1;
                    if (yy < 0 || yy >= HH) continue;
                    const bf16* rp = chp + yy * WW;
                    float rv[18];
                    rv[0] = (xb > 0) ? ldbf(rp + xb - 1) : 0.f;
                    unpack8(*reinterpret_cast<const uint4*>(rp + xb), rv + 1);
                    unpack8(*reinterpret_cast<const uint4*>(rp + xb + 8), rv + 9);
                    rv[17] = (xb + 16 < WW) ? ldbf(rp + xb + 16) : 0.f;
                    float w0 = wv[r * 3], w1 = wv[r * 3 + 1], w2 = wv[r * 3 + 2];
#pragma unroll
                    for (int i = 0; i < 16; ++i)
                        s1[i] += w0 * rv[i] + w1 * rv[i + 1] + w2 * rv[i + 2];
                }
#pragma unroll
                for (int i = 0; i < 16; ++i)
                    out[i] = 0.5f * s1[i] * (1.f + erff(s1[i] * 0.70710678118654752f));
            }
            {
                const float* wp = dww + (size_t)(k + HID) * 9;
                float wv[9];
#pragma unroll
                for (int i = 0; i < 9; ++i) wv[i] = __ldg(wp + i);
#pragma unroll
                for (int i = 0; i < 16; ++i) s1[i] = 0.f;
                const bf16* chp = Hb + (size_t)(k + HID) * PIX;
#pragma unroll
                for (int r = 0; r < 3; ++r) {
                    int yy = y + r - 1;
                    if (yy < 0 || yy >= HH) continue;
                    const bf16* rp = chp + yy * WW;
                    float rv[18];
                    rv[0] = (xb > 0) ? ldbf(rp + xb - 1) : 0.f;
                    unpack8(*reinterpret_cast<const uint4*>(rp + xb), rv + 1);
                    unpack8(*reinterpret_cast<const uint4*>(rp + xb + 8), rv + 9);
                    rv[17] = (xb + 16 < WW) ? ldbf(rp + xb + 16) : 0.f;
                    float w0 = wv[r * 3], w1 = wv[r * 3 + 1], w2 = wv[r * 3 + 2];
#pragma unroll
                    for (int i = 0; i < 16; ++i)
                        s1[i] += w0 * rv[i] + w1 * rv[i + 1] + w2 * rv[i + 2];
                }
#pragma unroll
                for (int i = 0; i < 16; ++i) out[i] *= s1[i];
            }
            store16(&Bs[kl * BNP3 + (t & 3) * 16], out);
        }
        if (kc == 1) {
            for (int i = tid; i < 2 * BNP3; i += 256)
                Bs[254 * BNP3 + i] = __float2bfloat16(0.f);
        }

        // ---- 3 m-tiles against this B chunk ----
        for (int mt = 0; mt < 3; ++mt) {
            cp_wait0();
            __syncthreads();
            if (pf < 6) {
                int pkc = pf / 3, pmt = pf % 3;
                const bf16* src = d_w3 + (size_t)pmt * 64 * 512 + pkc * 256;
                bf16* dst = Asb[pf & 1];
                for (int c = tid; c < 64 * 32; c += 256) {
                    int row = c >> 5, ch = c & 31;
                    cpasync16(&dst[row * KAP3 + ch * 8], src + row * 512 + ch * 8);
                }
                cp_commit();
            }
            const bf16* Ac = Asb[(kc * 3 + mt) & 1];

#pragma unroll 4
            for (int ks = 0; ks < 16; ++ks) {
                unsigned a[2][4];
#pragma unroll
                for (int mi = 0; mi < 2; ++mi) {
                    int row = wm + mi * 16 + (lane & 15);
                    int col = ks * 16 + ((lane >> 4) << 3);
                    ldsm4(a[mi][0], a[mi][1], a[mi][2], a[mi][3], &Ac[row * KAP3 + col]);
                }
                unsigned bq[4];
                {
                    int row = ks * 16 + ((lane >> 3) & 1) * 8 + (lane & 7);
                    int col = wn + ((lane >> 4) << 3);
                    ldsm4t(bq[0], bq[1], bq[2], bq[3], &Bs[row * BNP3 + col]);
                }
#pragma unroll
                for (int mi = 0; mi < 2; ++mi) {
                    mma16816(acc[mt][mi][0], a[mi], bq[0], bq[1]);
                    mma16816(acc[mt][mi][1], a[mi], bq[2], bq[3]);
                }
            }
            ++pf;
        }
    }

    // ---- epilogue: out = acc + x1 ----
    const int gg = lane >> 2;
    const int t2 = (lane & 3) * 2;
#pragma unroll
    for (int mt = 0; mt < 3; ++mt)
#pragma unroll
        for (int mi = 0; mi < 2; ++mi)
#pragma unroll
            for (int j = 0; j < 2; ++j) {
                int obase = mt * 64 + wm + mi * 16 + gg;
                int col   = n0 + wn + j * 8 + t2;
#pragma unroll
                for (int half = 0; half < 2; ++half) {
                    int o = obase + half * 8;
                    size_t off = (size_t)o * PIX + col;
                    float2 rv2 = *reinterpret_cast<const float2*>(&resb[off]);
                    float o0 = acc[mt][mi][j][half * 2 + 0] + rv2.x;
                    float o1 = acc[mt][mi][j][half * 2 + 1] + rv2.y;
                    *reinterpret_cast<float2*>(&out32[off]) = make_float2(o0, o1);
                }
            }
}

// ------- G = dw(Q) dw(K)^T + norms, dw fused, mma, register-light ------------
// grid (37 chunks of <=7 rows, BATCH*NHEADS) = 296 blocks = 148 SMs x 2 CTAs.
constexpr int QSTR = 264;   // bf16 row stride

__global__ __launch_bounds__(256, 2) void greduce_kernel(const float* __restrict__ w)
{
    extern __shared__ __align__(16) char gsm_raw[];
    bf16*  qs  = reinterpret_cast<bf16*>(gsm_raw);            // [48][QSTR]
    bf16*  ksm = qs + HD * QSTR;                              // [48][QSTR]
    float* wsm = reinterpret_cast<float*>(gsm_raw + 2 * HD * QSTR * 2);  // [96*9]
    float* nrm = wsm + 96 * 9;                                // [96]

    const int tid   = threadIdx.x;
    const int lane  = tid & 31;
    const int warp  = tid >> 5;
    const int chunk = blockIdx.x;        // 0..36
    const int hb    = blockIdx.y;        // 0..7
    const int b = hb >> 2, h = hb & 3;

    const int y0 = chunk * 7;
    const int ny = min(7, HH - y0);

    for (int i = tid; i < 96 * 9; i += 256) {
        int ch96 = i / 9, r = i - ch96 * 9;
        int gch = (ch96 < 48) ? (h * HD + ch96) : (CDIM + h * HD + ch96 - 48);
        wsm[i] = __ldg(&w[gch * 9 + r]);
    }
    if (tid < 96) nrm[tid] = 0.f;

    const int t_mt = warp / 3;           // warp7 -> 2
    const int t_nt = warp % 3;           // warp7 -> 1 (second tile nt=2)
    const bool two = (warp == 7);

    float acc[2][2][4];
#pragma unroll
    for (int ti = 0; ti < 2; ++ti)
#pragma unroll
        for (int lh = 0; lh < 2; ++lh)
#pragma unroll
            for (int q = 0; q < 4; ++q) acc[ti][lh][q] = 0.f;
    float nsq[6] = {0.f, 0.f, 0.f, 0.f, 0.f, 0.f};

    for (int y = y0; y < y0 + ny; ++y) {
        __syncthreads();    // wsm ready (iter0) / previous mma reads done
#pragma unroll
        for (int s = 0; s < 6; ++s) {
            int t = tid + s * 256;
            int seg  = t & 15;
            int ch96 = t >> 4;
            int gch = (ch96 < 48) ? (h * HD + ch96) : (CDIM + h * HD + ch96 - 48);
            const bf16* plane = d_qkv + ((size_t)b * QKVC + gch) * PIX;
            const float* wv = wsm + ch96 * 9;
            int x0 = seg * 16;
            float out[16];
#pragma unroll
            for (int i = 0; i < 16; ++i) out[i] = 0.f;
#pragma unroll
            for (int r = 0; r < 3; ++r) {
                int yy = y + r - 1;
                if (yy < 0 || yy >= HH) continue;
                const bf16* rp = plane + yy * WW;
                float rv[18];
                rv[0] = (x0 > 0) ? ldbf(rp + x0 - 1) : 0.f;
                unpack8(*reinterpret_cast<const uint4*>(rp + x0), rv + 1);
                unpack8(*reinterpret_cast<const uint4*>(rp + x0 + 8), rv + 9);
                rv[17] = (x0 + 16 < WW) ? ldbf(rp + x0 + 16) : 0.f;
                float w0 = wv[r * 3], w1 = wv[r * 3 + 1], w2 = wv[r * 3 + 2];
#pragma unroll
                for (int i = 0; i < 16; ++i)
                    out[i] += w0 * rv[i] + w1 * rv[i + 1] + w2 * rv[i + 2];
            }
            float ss = 0.f;
#pragma unroll
            for (int i = 0; i < 16; ++i) ss = fmaf(out[i], out[i], ss);
            nsq[s] += ss;
            bf16* dst = ((ch96 < 48) ? qs + ch96 * QSTR
                                     : ksm + (ch96 - 48) * QSTR) + x0;
            store16(dst, out);
        }
        __syncthreads();
#pragma unroll 4
        for (int ks = 0; ks < 16; ++ks) {
            const int kc = ks * 16 + ((lane >> 4) << 3);
            unsigned av[4];
            ldsm4(av[0], av[1], av[2], av[3],
                  &qs[(t_mt * 16 + (lane & 15)) * QSTR + kc]);
            unsigned bv[4];
            ldsm4(bv[0], bv[1], bv[2], bv[3],
                  &ksm[(t_nt * 16 + (lane & 15)) * QSTR + kc]);
            mma16816(acc[0][0], av, bv[0], bv[2]);
            mma16816(acc[0][1], av, bv[1], bv[3]);
            if (two) {
                unsigned bv2[4];
                ldsm4(bv2[0], bv2[1], bv2[2], bv2[3],
                      &ksm[(2 * 16 + (lane & 15)) * QSTR + kc]);
                mma16816(acc[1][0], av, bv2[0], bv2[2]);
                mma16816(acc[1][1], av, bv2[1], bv2[3]);
            }
        }
    }

    const size_t Goff = (size_t)(b * NHEADS + h) * HD * HD;
    const int mrow = lane >> 2;
    const int ncol = (lane & 3) * 2;
    const int ntile = two ? 2 : 1;
#pragma unroll
    for (int ti = 0; ti < 2; ++ti) {
        if (ti >= ntile) break;
        int nt = (ti == 0) ? t_nt : 2;
#pragma unroll
        for (int lh = 0; lh < 2; ++lh) {
            int m = t_mt * 16 + mrow;
            int n = nt * 16 + lh * 8 + ncol;
            atomicAdd(&d_G[Goff + m * HD + n],           acc[ti][lh][0]);
            atomicAdd(&d_G[Goff + m * HD + n + 1],       acc[ti][lh][1]);
            atomicAdd(&d_G[Goff + (m + 8) * HD + n],     acc[ti][lh][2]);
            atomicAdd(&d_G[Goff + (m + 8) * HD + n + 1], acc[ti][lh][3]);
        }
    }
#pragma unroll
    for (int s = 0; s < 6; ++s) {
        int ch96 = (tid + s * 256) >> 4;
        atomicAdd(&nrm[ch96], nsq[s]);
    }
    __syncthreads();
    const int gbase = (b * NHEADS + h) * HD;
    if (tid < HD)          atomicAdd(&d_qn[gbase + tid], nrm[tid]);
    else if (tid < 2 * HD) atomicAdd(&d_kn[gbase + tid - HD], nrm[tid]);
}

// ------------------- softmax(attn): one warp per row --------------------------
__global__ void attn_kernel(const float* __restrict__ temp)
{
    const int c    = blockIdx.x;          // 0..47
    const int hb   = blockIdx.y;          // 0..7
    const int b = hb >> 2, h = hb & 3;
    const int lane = threadIdx.x;         // 32
    const int base = (b * NHEADS + h) * HD;

    float qn = fmaxf(sqrtf(d_qn[base + c]), 1e-12f);
    float sc = __ldg(&temp[h]) / qn;

    float kn0 = fmaxf(sqrtf(d_kn[base + lane]), 1e-12f);
    float v0  = d_G[(base + c) * HD + lane] / kn0 * sc;
    float v1  = -1e30f;
    if (lane < 16) {
        float kn1 = fmaxf(sqrtf(d_kn[base + lane + 32]), 1e-12f);
        v1 = d_G[(base + c) * HD + lane + 32] / kn1 * sc;
    }
    float mx = fmaxf(v0, v1);
#pragma unroll
    for (int off = 16; off; off >>= 1)
        mx = fmaxf(mx, __shfl_xor_sync(0xffffffffu, mx, off));
    float e0 = expf(v0 - mx);
    float e1 = (lane < 16) ? expf(v1 - mx) : 0.f;
    float s = e0 + e1;
#pragma unroll
    for (int off = 16; off; off >>= 1)
        s += __shfl_xor_sync(0xffffffffu, s, off);
    float inv = 1.f / s;
    d_attn[(base + c) * HD + lane] = e0 * inv;
    if (lane < 16)
        d_attn[(base + c) * HD + lane + 32] = e1 * inv;
}

// ------------------- M = proj_w @ blockdiag(attn), bf16 out ------------------
__global__ void mmat_kernel(const float* __restrict__ projw)
{
    const int o = blockIdx.x;
    const int b = blockIdx.y;
    const int j = threadIdx.x;       // 0..191
    const int h = j / HD, dd = j % HD;
    const float* aw = d_attn + ((size_t)(b * NHEADS + h) * HD) * HD;
    const float* pw = projw + (size_t)o * CDIM + h * HD;
    float s = 0.f;
#pragma unroll
    for (int c = 0; c < HD; ++c)
        s = fmaf(__ldg(pw + c), aw[c * HD + dd], s);
    d_Mh[((size_t)b * CDIM + o) * CDIM + j] = __float2bfloat16(s);
}

// ----------------------------- launcher --------------------------------------
static inline int smem_bytes_for_mode(int mode)
{
    int base = 192 * 136 * 2 + 2 * 64 * 200 * 2;                       // 103424
    if (mode == 0) base += (2 * 128 + 2 * 192 + 2 * 128) * 4;          // +3584
    if (mode == 2) base += (2 * 128 + 2 * 192) * 4;                    // +2560
    if (mode == 1) base += 2 * 128 * 4;                                // +1024
    return base;
}
static constexpr int GEMM3_SMEM   = KC3 * BNP3 * 2 + 2 * 64 * KAP3 * 2;   // 104448
static constexpr int GREDUCE_SMEM = 2 * HD * QSTR * 2 + (96 * 9 + 96) * 4; // 54528

extern "C" void kernel_launch(void* const* d_in, const int* in_sizes, int n_in,
                              void* d_out, int out_size)
{
    const float* x        = (const float*)d_in[0];
    const float* ln1_w    = (const float*)d_in[1];
    const float* ln1_b    = (const float*)d_in[2];
    const float* temp     = (const float*)d_in[3];
    const float* qkv_w    = (const float*)d_in[4];
    const float* qkv_dw_w = (const float*)d_in[5];
    const float* proj_w   = (const float*)d_in[6];
    const float* ln2_w    = (const float*)d_in[7];
    const float* ln2_b    = (const float*)d_in[8];
    const float* ffn_in_w = (const float*)d_in[9];
    const float* ffn_dw_w = (const float*)d_in[10];
    const float* ffn_out_w= (const float*)d_in[11];
    float* out = (float*)d_out;

    static bool attr_done = false;
    if (!attr_done) {
        cudaFuncSetAttribute(gemm_mma<0>, cudaFuncAttributeMaxDynamicSharedMemorySize, smem_bytes_for_mode(0));
        cudaFuncSetAttribute(gemm_mma<1>, cudaFuncAttributeMaxDynamicSharedMemorySize, smem_bytes_for_mode(1));
        cudaFuncSetAttribute(gemm_mma<2>, cudaFuncAttributeMaxDynamicSharedMemorySize, smem_bytes_for_mode(2));
        cudaFuncSetAttribute(gemm3_kernel, cudaFuncAttributeMaxDynamicSharedMemorySize, GEMM3_SMEM);
        cudaFuncSetAttribute(greduce_kernel, cudaFuncAttributeMaxDynamicSharedMemorySize, GREDUCE_SMEM);
        attr_done = true;
    }

    const dim3 blk(256);

    // 1. weight pre-conversion to bf16 (padded) + attention stat zeroing
    prep_w_kernel<<<(FFNCP * CDIM + 255) / 256, blk>>>(qkv_w, ffn_in_w, ffn_out_w);

    // 2. qkv = qkv_w @ LN1(x)   (LN1 stats fused in-block)
    {
        dim3 grid(PIX / 128, BATCH);
        gemm_mma<0><<<grid, blk, smem_bytes_for_mode(0)>>>(x, ln1_w, ln1_b, nullptr, nullptr);
    }

    // 3. attention statistics (dw3x3 fused; mma; 296 blocks = 2 full waves)
    {
        dim3 grid(37, BATCH * NHEADS);
        greduce_kernel<<<grid, blk, GREDUCE_SMEM>>>(qkv_dw_w);
    }

    // 4. softmax (one warp per attention row)
    {
        dim3 grid(HD, BATCH * NHEADS);
        attn_kernel<<<grid, 32>>>(temp);
    }

    // 5. M = proj_w @ blockdiag(attn)
    {
        dim3 grid(CDIM, BATCH);
        mmat_kernel<<<grid, CDIM>>>(proj_w);
    }

    // 6. x1 = x + M @ dw(V)  (+ LN2 stats fused in epilogue)
    {
        dim3 grid(PIX / 128, BATCH);
        gemm_mma<1><<<grid, blk, smem_bytes_for_mode(1)>>>(nullptr, qkv_dw_w, nullptr, x, nullptr);
    }

    // 7. h = ffn_in_w @ LN2(x1)
    {
        dim3 grid(PIX / 128, BATCH);
        gemm_mma<2><<<grid, blk, smem_bytes_for_mode(2)>>>(nullptr, ln2_w, ln2_b, nullptr, nullptr);
    }

    // 8. out = x1 + ffn_out_w @ (gelu(dw(h1)) * dw(h2))  (k-chunked, 2 CTA/SM)
    {
        dim3 grid(PIX / 64, BATCH);
        gemm3_kernel<<<grid, blk, GEMM3_SMEM>>>(ffn_dw_w, out);
    }
}

// round 17
// speedup vs baseline: 1.0439x; 1.0439x over previous
#include <cuda_runtime.h>
#include <cuda_bf16.h>
#include <cstdint>
#include <cstddef>

using bf16 = __nv_bfloat16;

constexpr int BATCH  = 2;
constexpr int CDIM   = 192;
constexpr int HH     = 256;
constexpr int WW     = 256;
constexpr int PIX    = HH * WW;          // 65536
constexpr int NHEADS = 4;
constexpr int HD     = 48;               // CDIM / NHEADS
constexpr int HID    = 510;
constexpr int QKVC   = 3 * CDIM;         // 576
constexpr int FFNC   = 2 * HID;          // 1020
constexpr int FFNCP  = 1024;             // padded ffn channels

// ----------------------------- device scratch -------------------------------
__device__ bf16  d_qkv  [(size_t)BATCH * QKVC * PIX];     // conv1x1(qkv), bf16
__device__ float d_x1   [(size_t)BATCH * CDIM * PIX];     // x + attn branch
__device__ bf16  d_h    [(size_t)BATCH * FFNCP * PIX];    // ffn_in conv1x1 (padded)
__device__ float d_G   [BATCH * NHEADS * HD * HD];
__device__ float d_qn  [BATCH * NHEADS * HD];
__device__ float d_kn  [BATCH * NHEADS * HD];
__device__ float d_attn[BATCH * NHEADS * HD * HD];
// pre-converted bf16 weights
__device__ bf16  d_wq [QKVC * CDIM];          // qkv_w
__device__ bf16  d_w2 [FFNCP * CDIM];         // ffn_in_w, rows 1020..1023 zero
__device__ bf16  d_w3 [CDIM * 512];           // ffn_out_w, cols 510,511 zero
__device__ bf16  d_Mh [BATCH * CDIM * CDIM];  // proj_w @ blockdiag(attn)

// ----------------------------- helpers --------------------------------------
__device__ __forceinline__ float ldbf(const bf16* p)
{
    unsigned short u = __ldg(reinterpret_cast<const unsigned short*>(p));
    __nv_bfloat16_raw r; r.x = u;
    return __bfloat162float(bf16(r));
}

__device__ __forceinline__ void unpack8(uint4 u, float* f)
{
    unsigned v[4] = {u.x, u.y, u.z, u.w};
#pragma unroll
    for (int i = 0; i < 4; ++i) {
        __nv_bfloat162 h = *reinterpret_cast<__nv_bfloat162*>(&v[i]);
        f[i * 2]     = __low2float(h);
        f[i * 2 + 1] = __high2float(h);
    }
}

__device__ __forceinline__ void store16(bf16* dst, const float* f)
{
    uint4 u[2];
    unsigned* p = reinterpret_cast<unsigned*>(u);
#pragma unroll
    for (int i = 0; i < 8; ++i) {
        __nv_bfloat162 h(__float2bfloat16(f[i * 2]), __float2bfloat16(f[i * 2 + 1]));
        p[i] = *reinterpret_cast<unsigned*>(&h);
    }
    reinterpret_cast<uint4*>(dst)[0] = u[0];
    reinterpret_cast<uint4*>(dst)[1] = u[1];
}

__device__ __forceinline__ void ldsm4(unsigned& r0, unsigned& r1, unsigned& r2,
                                      unsigned& r3, const void* p)
{
    unsigned a = (unsigned)__cvta_generic_to_shared(p);
    asm volatile("ldmatrix.sync.aligned.m8n8.x4.shared.b16 {%0,%1,%2,%3}, [%4];"
                 : "=r"(r0), "=r"(r1), "=r"(r2), "=r"(r3) : "r"(a));
}
__device__ __forceinline__ void ldsm4t(unsigned& r0, unsigned& r1, unsigned& r2,
                                       unsigned& r3, const void* p)
{
    unsigned a = (unsigned)__cvta_generic_to_shared(p);
    asm volatile("ldmatrix.sync.aligned.m8n8.x4.trans.shared.b16 {%0,%1,%2,%3}, [%4];"
                 : "=r"(r0), "=r"(r1), "=r"(r2), "=r"(r3) : "r"(a));
}
__device__ __forceinline__ void mma16816(float (&d)[4], const unsigned (&a)[4],
                                         unsigned b0, unsigned b1)
{
    asm volatile(
        "mma.sync.aligned.m16n8k16.row.col.f32.bf16.bf16.f32 "
        "{%0,%1,%2,%3},{%4,%5,%6,%7},{%8,%9},{%0,%1,%2,%3};"
        : "+f"(d[0]), "+f"(d[1]), "+f"(d[2]), "+f"(d[3])
        : "r"(a[0]), "r"(a[1]), "r"(a[2]), "r"(a[3]), "r"(b0), "r"(b1));
}
__device__ __forceinline__ void cpasync16(void* dst, const void* src)
{
    unsigned d = (unsigned)__cvta_generic_to_shared(dst);
    asm volatile("cp.async.ca.shared.global [%0], [%1], 16;" :: "r"(d), "l"(src));
}
__device__ __forceinline__ void cp_commit()
{
    asm volatile("cp.async.commit_group;");
}
__device__ __forceinline__ void cp_wait0()
{
    asm volatile("cp.async.wait_group 0;");
}

// --------------- weight pre-conversion to bf16 + stats zeroing ---------------
__global__ __launch_bounds__(256) void prep_w_kernel(
    const float* __restrict__ qkv_w,
    const float* __restrict__ ffn_in_w,
    const float* __restrict__ ffn_out_w)
{
    int i = blockIdx.x * 256 + threadIdx.x;    // up to FFNCP*CDIM = 196608
    if (i < QKVC * CDIM)
        d_wq[i] = __float2bfloat16(__ldg(&qkv_w[i]));
    if (i < FFNCP * CDIM) {
        int r = i / CDIM;
        d_w2[i] = (r < FFNC) ? __float2bfloat16(__ldg(&ffn_in_w[i]))
                             : __float2bfloat16(0.f);
    }
    if (i < CDIM * 512) {
        int r = i >> 9, c = i & 511;
        d_w3[i] = (c < HID) ? __float2bfloat16(__ldg(&ffn_out_w[r * HID + c]))
                            : __float2bfloat16(0.f);
    }
    if (i < BATCH * NHEADS * HD * HD) d_G[i] = 0.f;
    if (i < BATCH * NHEADS * HD) { d_qn[i] = 0.f; d_kn[i] = 0.f; }
}

// ----------------------------- gemm0 (mma.sync) ------------------------------
// d_qkv[b,o,p] = sum_k wq[o,k] * LN1(x)[k,p], LN1 stats fused in-block.
__global__ __launch_bounds__(256) void gemm0_kernel(
    const float* __restrict__ Barg,     // x
    const float* __restrict__ lnw,
    const float* __restrict__ lnb)
{
    constexpr int  O   = QKVC;
    constexpr int  KP  = 192;
    constexpr int  BN  = 128;
    constexpr int  BNP = BN + 8;
    constexpr int  KAP = KP + 8;
    constexpr int  MT  = O / 64;
    constexpr int  WN  = BN / 4;
    constexpr int  WNF = WN / 8;
    constexpr int  NP  = WNF / 2;
    constexpr int  ACH = KP / 8;

    extern __shared__ __align__(16) char smem_raw[];
    bf16* Bs  = reinterpret_cast<bf16*>(smem_raw);                       // [KP][BNP]
    bf16* As0 = reinterpret_cast<bf16*>(smem_raw + KP * BNP * 2);        // 2x [64][KAP]
    bf16* Asb[2] = {As0, As0 + 64 * KAP};
    float* fdyn = reinterpret_cast<float*>(smem_raw + KP * BNP * 2 + 2 * 64 * KAP * 2);
    float* mu_s  = fdyn;                 // [BN]
    float* rs_s  = fdyn + BN;            // [BN]
    float* lnw_s = fdyn + 2 * BN;        // [KP]
    float* lnb_s = fdyn + 2 * BN + KP;   // [KP]
    float* s_cs  = fdyn + 2 * BN + 2 * KP;        // [BN]
    float* s_cq  = fdyn + 2 * BN + 2 * KP + BN;   // [BN]

    const int b    = blockIdx.y;
    const int n0   = blockIdx.x * BN;
    const int tid  = threadIdx.x;
    const int lane = tid & 31;
    const int warp = tid >> 5;
    const int wm   = (warp >> 2) * 32;
    const int wn   = (warp & 3) * WN;

    const bf16* Ab = d_wq;
    const float* Bf = Barg + (size_t)b * CDIM * PIX;
    bf16* out16 = d_qkv + (size_t)b * QKVC * PIX;

    {
        for (int c = tid; c < 64 * ACH; c += 256) {
            int row = c / ACH, ch = c % ACH;
            cpasync16(&Asb[0][row * KAP + ch * 8], Ab + row * KP + ch * 8);
        }
        cp_commit();
    }

    if (tid < BN) { s_cs[tid] = 0.f; s_cq[tid] = 0.f; }
    for (int i = tid; i < KP; i += 256) {
        lnw_s[i] = __ldg(&lnw[i]);
        lnb_s[i] = __ldg(&lnb[i]);
    }
    __syncthreads();
    const int c = (tid & 63) * 2;
    {
        float cs0 = 0.f, cq0 = 0.f, cs1 = 0.f, cq1 = 0.f;
        for (int e = tid; e < KP * BN / 2; e += 256) {
            int k = e >> 6;
            float2 xv = *reinterpret_cast<const float2*>(&Bf[(size_t)k * PIX + n0 + c]);
            cs0 += xv.x; cq0 = fmaf(xv.x, xv.x, cq0);
            cs1 += xv.y; cq1 = fmaf(xv.y, xv.y, cq1);
            __nv_bfloat162 hh(__float2bfloat16(xv.x), __float2bfloat16(xv.y));
            *reinterpret_cast<__nv_bfloat162*>(&Bs[k * BNP + c]) = hh;
        }
        atomicAdd(&s_cs[c],     cs0); atomicAdd(&s_cq[c],     cq0);
        atomicAdd(&s_cs[c + 1], cs1); atomicAdd(&s_cq[c + 1], cq1);
    }
    __syncthreads();
    if (tid < BN) {
        float mu  = s_cs[tid] * (1.f / CDIM);
        float var = fmaxf(s_cq[tid] * (1.f / CDIM) - mu * mu, 0.f);
        mu_s[tid] = mu;
        rs_s[tid] = rsqrtf(var + 1e-5f);
    }
    __syncthreads();
    for (int e = tid; e < KP * BN / 2; e += 256) {
        int k = e >> 6;
        __nv_bfloat162 hh = *reinterpret_cast<__nv_bfloat162*>(&Bs[k * BNP + c]);
        float v0 = (__low2float(hh)  - mu_s[c])     * rs_s[c]     * lnw_s[k] + lnb_s[k];
        float v1 = (__high2float(hh) - mu_s[c + 1]) * rs_s[c + 1] * lnw_s[k] + lnb_s[k];
        *reinterpret_cast<__nv_bfloat162*>(&Bs[k * BNP + c]) =
            __nv_bfloat162(__float2bfloat16(v0), __float2bfloat16(v1));
    }

    const int gg = lane >> 2;
    const int t2 = (lane & 3) * 2;

    for (int mt = 0; mt < MT; ++mt) {
        cp_wait0();
        __syncthreads();
        if (mt + 1 < MT) {
            const bf16* src = Ab + (size_t)(mt + 1) * 64 * KP;
            bf16* dst = Asb[(mt + 1) & 1];
            for (int cc = tid; cc < 64 * ACH; cc += 256) {
                int row = cc / ACH, ch = cc % ACH;
                cpasync16(&dst[row * KAP + ch * 8], src + row * KP + ch * 8);
            }
            cp_commit();
        }
        const bf16* Ac = Asb[mt & 1];
        const int m0 = mt * 64;

        float acc[2][WNF][4];
#pragma unroll
        for (int mi = 0; mi < 2; ++mi)
#pragma unroll
            for (int j = 0; j < WNF; ++j)
#pragma unroll
                for (int q = 0; q < 4; ++q) acc[mi][j][q] = 0.f;

#pragma unroll 4
        for (int ks = 0; ks < KP / 16; ++ks) {
            unsigned a[2][4];
#pragma unroll
            for (int mi = 0; mi < 2; ++mi) {
                int row = wm + mi * 16 + (lane & 15);
                int col = ks * 16 + ((lane >> 4) << 3);
                ldsm4(a[mi][0], a[mi][1], a[mi][2], a[mi][3], &Ac[row * KAP + col]);
            }
            unsigned bq[NP][4];
#pragma unroll
            for (int p = 0; p < NP; ++p) {
                int row = ks * 16 + ((lane >> 3) & 1) * 8 + (lane & 7);
                int col = wn + p * 16 + ((lane >> 4) << 3);
                ldsm4t(bq[p][0], bq[p][1], bq[p][2], bq[p][3], &Bs[row * BNP + col]);
            }
#pragma unroll
            for (int mi = 0; mi < 2; ++mi)
#pragma unroll
                for (int j = 0; j < WNF; ++j) {
                    int p = j >> 1;
                    if ((j & 1) == 0) mma16816(acc[mi][j], a[mi], bq[p][0], bq[p][1]);
                    else              mma16816(acc[mi][j], a[mi], bq[p][2], bq[p][3]);
                }
        }

#pragma unroll
        for (int mi = 0; mi < 2; ++mi)
#pragma unroll
            for (int j = 0; j < WNF; ++j) {
                int obase = m0 + wm + mi * 16 + gg;
                int col   = n0 + wn + j * 8 + t2;
#pragma unroll
                for (int half = 0; half < 2; ++half) {
                    int o = obase + half * 8;
                    __nv_bfloat162 pk(__float2bfloat16(acc[mi][j][half * 2 + 0]),
                                      __float2bfloat16(acc[mi][j][half * 2 + 1]));
                    *reinterpret_cast<__nv_bfloat162*>(&out16[(size_t)o * PIX + col]) = pk;
                }
            }
    }
}

// ------- fused gemm1+gemm2: x1 = x + M@dw(V); h = ffn_in_w @ LN2(x1) ---------
// One block owns a 128-pixel strip. Phase A produces all 192 x1 channels
// (fp32 to global for gemm3's residual) + LN2 stats in smem; phase B reads
// x1 back (L2-hot) and runs the 16-m-tile ffn_in GEMM.
__global__ __launch_bounds__(256) void gemm12_kernel(
    const float* __restrict__ dww,      // qkv_dw_w
    const float* __restrict__ ln2w,
    const float* __restrict__ ln2b,
    const float* __restrict__ resArg)   // x
{
    constexpr int  KP  = 192;
    constexpr int  BN  = 128;
    constexpr int  BNP = BN + 8;
    constexpr int  KAP = KP + 8;
    constexpr int  WN  = BN / 4;
    constexpr int  WNF = WN / 8;
    constexpr int  NP  = WNF / 2;
    constexpr int  ACH = KP / 8;

    extern __shared__ __align__(16) char smem_raw[];
    bf16* Bs  = reinterpret_cast<bf16*>(smem_raw);                       // [KP][BNP]
    bf16* As0 = reinterpret_cast<bf16*>(smem_raw + KP * BNP * 2);        // 2x [64][KAP]
    bf16* Asb[2] = {As0, As0 + 64 * KAP};
    float* fdyn = reinterpret_cast<float*>(smem_raw + KP * BNP * 2 + 2 * 64 * KAP * 2);
    float* s_cs  = fdyn;                 // [BN] -> becomes mu
    float* s_cq  = fdyn + BN;            // [BN] -> becomes rs
    float* lnw_s = fdyn + 2 * BN;        // [KP]
    float* lnb_s = fdyn + 2 * BN + KP;   // [KP]

    const int b    = blockIdx.y;
    const int n0   = blockIdx.x * BN;
    const int tid  = threadIdx.x;
    const int lane = tid & 31;
    const int warp = tid >> 5;
    const int wm   = (warp >> 2) * 32;
    const int wn   = (warp & 3) * WN;
    const int gg   = lane >> 2;
    const int t2   = (lane & 3) * 2;

    const bf16*  Ab1  = d_Mh + (size_t)b * CDIM * CDIM;
    const float* resb = resArg + (size_t)b * CDIM * PIX;
    float* x1b        = d_x1 + (size_t)b * CDIM * PIX;
    bf16*  hb         = d_h + (size_t)b * FFNCP * PIX;

    // ---- phase A: prefetch M tile 0 ----
    {
        for (int cc = tid; cc < 64 * ACH; cc += 256) {
            int row = cc / ACH, ch = cc % ACH;
            cpasync16(&Asb[0][row * KAP + ch * 8], Ab1 + row * KP + ch * 8);
        }
        cp_commit();
    }

    if (tid < BN) { s_cs[tid] = 0.f; s_cq[tid] = 0.f; }
    for (int i = tid; i < KP; i += 256) {
        lnw_s[i] = __ldg(&ln2w[i]);
        lnb_s[i] = __ldg(&ln2b[i]);
    }

    // ---- phase A: B fill = dw3x3(V) on the fly ----
    {
        const bf16* Vb = d_qkv + ((size_t)b * QKVC + 2 * CDIM) * PIX;
        const int y  = n0 >> 8;
        const int xs = n0 & 255;
        for (int t = tid; t < CDIM * 8; t += 256) {
            int k  = t >> 3;
            int xb = xs + (t & 7) * 16;
            const float* wp = dww + (size_t)(2 * CDIM + k) * 9;
            float wv[9];
#pragma unroll
            for (int i = 0; i < 9; ++i) wv[i] = __ldg(wp + i);
            float out[16];
#pragma unroll
            for (int i = 0; i < 16; ++i) out[i] = 0.f;
            const bf16* chp = Vb + (size_t)k * PIX;
#pragma unroll
            for (int r = 0; r < 3; ++r) {
                int yy = y + r - 1;
                if (yy < 0 || yy >= HH) continue;
                const bf16* rp = chp + yy * WW;
                float rv[18];
                rv[0] = (xb > 0) ? ldbf(rp + xb - 1) : 0.f;
                unpack8(*reinterpret_cast<const uint4*>(rp + xb), rv + 1);
                unpack8(*reinterpret_cast<const uint4*>(rp + xb + 8), rv + 9);
                rv[17] = (xb + 16 < WW) ? ldbf(rp + xb + 16) : 0.f;
                float w0 = wv[r * 3], w1 = wv[r * 3 + 1], w2 = wv[r * 3 + 2];
#pragma unroll
                for (int i = 0; i < 16; ++i)
                    out[i] += w0 * rv[i] + w1 * rv[i + 1] + w2 * rv[i + 2];
            }
            store16(&Bs[k * BNP + (t & 7) * 16], out);
        }
    }

    float cs[8], cq[8];
#pragma unroll
    for (int j = 0; j < 8; ++j) { cs[j] = 0.f; cq[j] = 0.f; }

    // ---- phase A mainloop: 3 m-tiles over M (d_Mh) ----
    for (int mt = 0; mt < 3; ++mt) {
        cp_wait0();
        __syncthreads();
        if (mt + 1 < 3) {
            const bf16* src = Ab1 + (size_t)(mt + 1) * 64 * KP;
            bf16* dst = Asb[(mt + 1) & 1];
            for (int cc = tid; cc < 64 * ACH; cc += 256) {
                int row = cc / ACH, ch = cc % ACH;
                cpasync16(&dst[row * KAP + ch * 8], src + row * KP + ch * 8);
            }
            cp_commit();
        }
        const bf16* Ac = Asb[mt & 1];
        const int m0 = mt * 64;

        float acc[2][WNF][4];
#pragma unroll
        for (int mi = 0; mi < 2; ++mi)
#pragma unroll
            for (int j = 0; j < WNF; ++j)
#pragma unroll
                for (int q = 0; q < 4; ++q) acc[mi][j][q] = 0.f;

#pragma unroll 4
        for (int ks = 0; ks < KP / 16; ++ks) {
            unsigned a[2][4];
#pragma unroll
            for (int mi = 0; mi < 2; ++mi) {
                int row = wm + mi * 16 + (lane & 15);
                int col = ks * 16 + ((lane >> 4) << 3);
                ldsm4(a[mi][0], a[mi][1], a[mi][2], a[mi][3], &Ac[row * KAP + col]);
            }
            unsigned bq[NP][4];
#pragma unroll
            for (int p = 0; p < NP; ++p) {
                int row = ks * 16 + ((lane >> 3) & 1) * 8 + (lane & 7);
                int col = wn + p * 16 + ((lane >> 4) << 3);
                ldsm4t(bq[p][0], bq[p][1], bq[p][2], bq[p][3], &Bs[row * BNP + col]);
            }
#pragma unroll
            for (int mi = 0; mi < 2; ++mi)
#pragma unroll
                for (int j = 0; j < WNF; ++j) {
                    int p = j >> 1;
                    if ((j & 1) == 0) mma16816(acc[mi][j], a[mi], bq[p][0], bq[p][1]);
                    else              mma16816(acc[mi][j], a[mi], bq[p][2], bq[p][3]);
                }
        }

#pragma unroll
        for (int mi = 0; mi < 2; ++mi)
#pragma unroll
            for (int j = 0; j < WNF; ++j) {
                int obase = m0 + wm + mi * 16 + gg;
                int col   = n0 + wn + j * 8 + t2;
#pragma unroll
                for (int half = 0; half < 2; ++half) {
                    int o = obase + half * 8;
                    size_t off = (size_t)o * PIX + col;
                    float2 rv2 = *reinterpret_cast<const float2*>(&resb[off]);
                    float o0 = acc[mi][j][half * 2 + 0] + rv2.x;
                    float o1 = acc[mi][j][half * 2 + 1] + rv2.y;
                    *reinterpret_cast<float2*>(&x1b[off]) = make_float2(o0, o1);
                    cs[j * 2]     += o0; cq[j * 2]     += o0 * o0;
                    cs[j * 2 + 1] += o1; cq[j * 2 + 1] += o1 * o1;
                }
            }
    }

    // ---- LN2 stats -> smem (no global round trip) ----
#pragma unroll
    for (int s = 0; s < 8; ++s) {
#pragma unroll
        for (int off = 4; off < 32; off <<= 1) {
            cs[s] += __shfl_xor_sync(0xffffffffu, cs[s], off);
            cq[s] += __shfl_xor_sync(0xffffffffu, cq[s], off);
        }
    }
    if (gg == 0) {
#pragma unroll
        for (int s = 0; s < 8; ++s) {
            int cc = wn + (s >> 1) * 8 + t2 + (s & 1);
            atomicAdd(&s_cs[cc], cs[s]);
            atomicAdd(&s_cq[cc], cq[s]);
        }
    }
    __syncthreads();
    if (tid < BN) {
        float mu  = s_cs[tid] * (1.f / CDIM);
        float var = fmaxf(s_cq[tid] * (1.f / CDIM) - mu * mu, 0.f);
        s_cs[tid] = mu;                  // alias: mu
        s_cq[tid] = rsqrtf(var + 1e-5f); // alias: rs
    }
    __syncthreads();

    // ---- phase B: prefetch ffn_in tile 0 ----
    {
        for (int cc = tid; cc < 64 * ACH; cc += 256) {
            int row = cc / ACH, ch = cc % ACH;
            cpasync16(&Asb[0][row * KAP + ch * 8], d_w2 + row * KP + ch * 8);
        }
        cp_commit();
    }

    // ---- phase B: B fill = LN2(x1), x1 read back L2-hot ----
    {
        const int c = (tid & 63) * 2;
        float mu0 = s_cs[c], rs0 = s_cq[c], mu1 = s_cs[c + 1], rs1 = s_cq[c + 1];
        for (int e = tid; e < KP * BN / 2; e += 256) {
            int k = e >> 6;
            float2 xv = *reinterpret_cast<const float2*>(&x1b[(size_t)k * PIX + n0 + c]);
            float v0 = (xv.x - mu0) * rs0 * lnw_s[k] + lnb_s[k];
            float v1 = (xv.y - mu1) * rs1 * lnw_s[k] + lnb_s[k];
            __nv_bfloat162 h(__float2bfloat16(v0), __float2bfloat16(v1));
            *reinterpret_cast<__nv_bfloat162*>(&Bs[k * BNP + c]) = h;
        }
    }

    // ---- phase B mainloop: 16 m-tiles over ffn_in_w ----
    for (int mt = 0; mt < 16; ++mt) {
        cp_wait0();
        __syncthreads();
        if (mt + 1 < 16) {
            const bf16* src = d_w2 + (size_t)(mt + 1) * 64 * KP;
            bf16* dst = Asb[(mt + 1) & 1];
            for (int cc = tid; cc < 64 * ACH; cc += 256) {
                int row = cc / ACH, ch = cc % ACH;
                cpasync16(&dst[row * KAP + ch * 8], src + row * KP + ch * 8);
            }
            cp_commit();
        }
        const bf16* Ac = Asb[mt & 1];
        const int m0 = mt * 64;

        float acc[2][WNF][4];
#pragma unroll
        for (int mi = 0; mi < 2; ++mi)
#pragma unroll
            for (int j = 0; j < WNF; ++j)
#pragma unroll
                for (int q = 0; q < 4; ++q) acc[mi][j][q] = 0.f;

#pragma unroll 4
        for (int ks = 0; ks < KP / 16; ++ks) {
            unsigned a[2][4];
#pragma unroll
            for (int mi = 0; mi < 2; ++mi) {
                int row = wm + mi * 16 + (lane & 15);
                int col = ks * 16 + ((lane >> 4) << 3);
                ldsm4(a[mi][0], a[mi][1], a[mi][2], a[mi][3], &Ac[row * KAP + col]);
            }
            unsigned bq[NP][4];
#pragma unroll
            for (int p = 0; p < NP; ++p) {
                int row = ks * 16 + ((lane >> 3) & 1) * 8 + (lane & 7);
                int col = wn + p * 16 + ((lane >> 4) << 3);
                ldsm4t(bq[p][0], bq[p][1], bq[p][2], bq[p][3], &Bs[row * BNP + col]);
            }
#pragma unroll
            for (int mi = 0; mi < 2; ++mi)
#pragma unroll
                for (int j = 0; j < WNF; ++j) {
                    int p = j >> 1;
                    if ((j & 1) == 0) mma16816(acc[mi][j], a[mi], bq[p][0], bq[p][1]);
                    else              mma16816(acc[mi][j], a[mi], bq[p][2], bq[p][3]);
                }
        }

#pragma unroll
        for (int mi = 0; mi < 2; ++mi)
#pragma unroll
            for (int j = 0; j < WNF; ++j) {
                int obase = m0 + wm + mi * 16 + gg;
                int col   = n0 + wn + j * 8 + t2;
#pragma unroll
                for (int half = 0; half < 2; ++half) {
                    int o = obase + half * 8;
                    __nv_bfloat162 pk(__float2bfloat16(acc[mi][j][half * 2 + 0]),
                                      __float2bfloat16(acc[mi][j][half * 2 + 1]));
                    *reinterpret_cast<__nv_bfloat162*>(&hb[(size_t)o * PIX + col]) = pk;
                }
            }
    }
}

// ------------------- gemm3: out = x1 + ffn_out_w @ gate(dw(h)) ---------------
constexpr int KC3  = 256;
constexpr int BNP3 = 72;
constexpr int KAP3 = 264;

__global__ __launch_bounds__(256, 2) void gemm3_kernel(
    const float* __restrict__ dww,      // ffn_dw_w
    float* __restrict__ outArg)
{
    extern __shared__ __align__(16) char smem_raw[];
    bf16* Bs  = reinterpret_cast<bf16*>(smem_raw);                       // [256][72]
    bf16* As0 = reinterpret_cast<bf16*>(smem_raw + KC3 * BNP3 * 2);      // 2x [64][264]
    bf16* Asb[2] = {As0, As0 + 64 * KAP3};

    const int b    = blockIdx.y;
    const int n0   = blockIdx.x * 64;
    const int tid  = threadIdx.x;
    const int lane = tid & 31;
    const int warp = tid >> 5;
    const int wm   = (warp >> 2) * 32;
    const int wn   = (warp & 3) * 16;

    const bf16*  Hb   = d_h + (size_t)b * FFNCP * PIX;
    const float* resb = d_x1 + (size_t)b * CDIM * PIX;
    float* out32      = outArg + (size_t)b * CDIM * PIX;

    for (int c = tid; c < 64 * 32; c += 256) {
        int row = c >> 5, ch = c & 31;
        cpasync16(&Asb[0][row * KAP3 + ch * 8], d_w3 + row * 512 + ch * 8);
    }
    cp_commit();

    float acc[3][2][2][4];
#pragma unroll
    for (int mt = 0; mt < 3; ++mt)
#pragma unroll
        for (int mi = 0; mi < 2; ++mi)
#pragma unroll
            for (int j = 0; j < 2; ++j)
#pragma unroll
                for (int q = 0; q < 4; ++q) acc[mt][mi][j][q] = 0.f;

    const int y  = n0 >> 8;
    const int xs = n0 & 255;

    int pf = 1;
    for (int kc = 0; kc < 2; ++kc) {
        if (kc) __syncthreads();
        const int kbase = kc * 256;
        const int nch   = (kc == 0) ? 256 : 254;
        for (int t = tid; t < nch * 4; t += 256) {
            int kl = t >> 2;
            int k  = kbase + kl;
            int xb = xs + (t & 3) * 16;
            float s1[16], out[16];
            {
                const float* wp = dww + (size_t)k * 9;
                float wv[9];
#pragma unroll
                for (int i = 0; i < 9; ++i) wv[i] = __ldg(wp + i);
#pragma unroll
                for (int i = 0; i < 16; ++i) s1[i] = 0.f;
                const bf16* chp = Hb + (size_t)k * PIX;
#pragma unroll
                for (int r = 0; r < 3; ++r) {
                    int yy = y + r - 1;
                    if (yy < 0 || yy >= HH) continue;
                    const bf16* rp = chp + yy * WW;
                    float rv[18];
                    rv[0] = (xb > 0) ? ldbf(rp + xb - 1) : 0.f;
                    unpack8(*reinterpret_cast<const uint4*>(rp + xb), rv + 1);
                    unpack8(*reinterpret_cast<const uint4*>(rp + xb + 8), rv + 9);
                    rv[17] = (xb + 16 < WW) ? ldbf(rp + xb + 16) : 0.f;
                    float w0 = wv[r * 3], w1 = wv[r * 3 + 1], w2 = wv[r * 3 + 2];
#pragma unroll
                    for (int i = 0; i < 16; ++i)
                        s1[i] += w0 * rv[i] + w1 * rv[i + 1] + w2 * rv[i + 2];
                }
#pragma unroll
                for (int i = 0; i < 16; ++i)
                    out[i] = 0.5f * s1[i] * (1.f + erff(s1[i] * 0.70710678118654752f));
            }
            {
                const float* wp = dww + (size_t)(k + HID) * 9;
                float wv[9];
#pragma unroll
                for (int i = 0; i < 9; ++i) wv[i] = __ldg(wp + i);
#pragma unroll
                for (int i = 0; i < 16; ++i) s1[i] = 0.f;
                const bf16* chp = Hb + (size_t)(k + HID) * PIX;
#pragma unroll
                for (int r = 0; r < 3; ++r) {
                    int yy = y + r - 1;
                    if (yy < 0 || yy >= HH) continue;
                    const bf16* rp = chp + yy * WW;
                    float rv[18];
                    rv[0] = (xb > 0) ? ldbf(rp + xb - 1) : 0.f;
                    unpack8(*reinterpret_cast<const uint4*>(rp + xb), rv + 1);
                    unpack8(*reinterpret_cast<const uint4*>(rp + xb + 8), rv + 9);
                    rv[17] = (xb + 16 < WW) ? ldbf(rp + xb + 16) : 0.f;
                    float w0 = wv[r * 3], w1 = wv[r * 3 + 1], w2 = wv[r * 3 + 2];
#pragma unroll
                    for (int i = 0; i < 16; ++i)
                        s1[i] += w0 * rv[i] + w1 * rv[i + 1] + w2 * rv[i + 2];
                }
#pragma unroll
                for (int i = 0; i < 16; ++i) out[i] *= s1[i];
            }
            store16(&Bs[kl * BNP3 + (t & 3) * 16], out);
        }
        if (kc == 1) {
            for (int i = tid; i < 2 * BNP3; i += 256)
                Bs[254 * BNP3 + i] = __float2bfloat16(0.f);
        }

        for (int mt = 0; mt < 3; ++mt) {
            cp_wait0();
            __syncthreads();
            if (pf < 6) {
                int pkc = pf / 3, pmt = pf % 3;
                const bf16* src = d_w3 + (size_t)pmt * 64 * 512 + pkc * 256;
                bf16* dst = Asb[pf & 1];
                for (int c = tid; c < 64 * 32; c += 256) {
                    int row = c >> 5, ch = c & 31;
                    cpasync16(&dst[row * KAP3 + ch * 8], src + row * 512 + ch * 8);
                }
                cp_commit();
            }
            const bf16* Ac = Asb[(kc * 3 + mt) & 1];

#pragma unroll 4
            for (int ks = 0; ks < 16; ++ks) {
                unsigned a[2][4];
#pragma unroll
                for (int mi = 0; mi < 2; ++mi) {
                    int row = wm + mi * 16 + (lane & 15);
                    int col = ks * 16 + ((lane >> 4) << 3);
                    ldsm4(a[mi][0], a[mi][1], a[mi][2], a[mi][3], &Ac[row * KAP3 + col]);
                }
                unsigned bq[4];
                {
                    int row = ks * 16 + ((lane >> 3) & 1) * 8 + (lane & 7);
                    int col = wn + ((lane >> 4) << 3);
                    ldsm4t(bq[0], bq[1], bq[2], bq[3], &Bs[row * BNP3 + col]);
                }
#pragma unroll
                for (int mi = 0; mi < 2; ++mi) {
                    mma16816(acc[mt][mi][0], a[mi], bq[0], bq[1]);
                    mma16816(acc[mt][mi][1], a[mi], bq[2], bq[3]);
                }
            }
            ++pf;
        }
    }

    const int gg = lane >> 2;
    const int t2 = (lane & 3) * 2;
#pragma unroll
    for (int mt = 0; mt < 3; ++mt)
#pragma unroll
        for (int mi = 0; mi < 2; ++mi)
#pragma unroll
            for (int j = 0; j < 2; ++j) {
                int obase = mt * 64 + wm + mi * 16 + gg;
                int col   = n0 + wn + j * 8 + t2;
#pragma unroll
                for (int half = 0; half < 2; ++half) {
                    int o = obase + half * 8;
                    size_t off = (size_t)o * PIX + col;
                    float2 rv2 = *reinterpret_cast<const float2*>(&resb[off]);
                    float o0 = acc[mt][mi][j][half * 2 + 0] + rv2.x;
                    float o1 = acc[mt][mi][j][half * 2 + 1] + rv2.y;
                    *reinterpret_cast<float2*>(&out32[off]) = make_float2(o0, o1);
                }
            }
}

// ------- G = dw(Q) dw(K)^T + norms, dw fused, mma, register-light ------------
// grid (37 chunks of <=7 rows, BATCH*NHEADS) = 296 blocks = 148 SMs x 2 CTAs.
constexpr int QSTR = 264;   // bf16 row stride

__global__ __launch_bounds__(256, 2) void greduce_kernel(const float* __restrict__ w)
{
    extern __shared__ __align__(16) char gsm_raw[];
    bf16*  qs  = reinterpret_cast<bf16*>(gsm_raw);            // [48][QSTR]
    bf16*  ksm = qs + HD * QSTR;                              // [48][QSTR]
    float* wsm = reinterpret_cast<float*>(gsm_raw + 2 * HD * QSTR * 2);  // [96*9]
    float* nrm = wsm + 96 * 9;                                // [96]

    const int tid   = threadIdx.x;
    const int lane  = tid & 31;
    const int warp  = tid >> 5;
    const int chunk = blockIdx.x;        // 0..36
    const int hb    = blockIdx.y;        // 0..7
    const int b = hb >> 2, h = hb & 3;

    const int y0 = chunk * 7;
    const int ny = min(7, HH - y0);

    for (int i = tid; i < 96 * 9; i += 256) {
        int ch96 = i / 9, r = i - ch96 * 9;
        int gch = (ch96 < 48) ? (h * HD + ch96) : (CDIM + h * HD + ch96 - 48);
        wsm[i] = __ldg(&w[gch * 9 + r]);
    }
    if (tid < 96) nrm[tid] = 0.f;

    const int t_mt = warp / 3;           // warp7 -> 2
    const int t_nt = warp % 3;           // warp7 -> 1 (second tile nt=2)
    const bool two = (warp == 7);

    float acc[2][2][4];
#pragma unroll
    for (int ti = 0; ti < 2; ++ti)
#pragma unroll
        for (int lh = 0; lh < 2; ++lh)
#pragma unroll
            for (int q = 0; q < 4; ++q) acc[ti][lh][q] = 0.f;
    float nsq[6] = {0.f, 0.f, 0.f, 0.f, 0.f, 0.f};

    for (int y = y0; y < y0 + ny; ++y) {
        __syncthreads();    // wsm ready (iter0) / previous mma reads done
#pragma unroll
        for (int s = 0; s < 6; ++s) {
            int t = tid + s * 256;
            int seg  = t & 15;
            int ch96 = t >> 4;
            int gch = (ch96 < 48) ? (h * HD + ch96) : (CDIM + h * HD + ch96 - 48);
            const bf16* plane = d_qkv + ((size_t)b * QKVC + gch) * PIX;
            const float* wv = wsm + ch96 * 9;
            int x0 = seg * 16;
            float out[16];
#pragma unroll
            for (int i = 0; i < 16; ++i) out[i] = 0.f;
#pragma unroll
            for (int r = 0; r < 3; ++r) {
                int yy = y + r - 1;
                if (yy < 0 || yy >= HH) continue;
                const bf16* rp = plane + yy * WW;
                float rv[18];
                rv[0] = (x0 > 0) ? ldbf(rp + x0 - 1) : 0.f;
                unpack8(*reinterpret_cast<const uint4*>(rp + x0), rv + 1);
                unpack8(*reinterpret_cast<const uint4*>(rp + x0 + 8), rv + 9);
                rv[17] = (x0 + 16 < WW) ? ldbf(rp + x0 + 16) : 0.f;
                float w0 = wv[r * 3], w1 = wv[r * 3 + 1], w2 = wv[r * 3 + 2];
#pragma unroll
                for (int i = 0; i < 16; ++i)
                    out[i] += w0 * rv[i] + w1 * rv[i + 1] + w2 * rv[i + 2];
            }
            float ss = 0.f;
#pragma unroll
            for (int i = 0; i < 16; ++i) ss = fmaf(out[i], out[i], ss);
            nsq[s] += ss;
            bf16* dst = ((ch96 < 48) ? qs + ch96 * QSTR
                                     : ksm + (ch96 - 48) * QSTR) + x0;
            store16(dst, out);
        }
        __syncthreads();
#pragma unroll 4
        for (int ks = 0; ks < 16; ++ks) {
            const int kc = ks * 16 + ((lane >> 4) << 3);
            unsigned av[4];
            ldsm4(av[0], av[1], av[2], av[3],
                  &qs[(t_mt * 16 + (lane & 15)) * QSTR + kc]);
            unsigned bv[4];
            ldsm4(bv[0], bv[1], bv[2], bv[3],
                  &ksm[(t_nt * 16 + (lane & 15)) * QSTR + kc]);
            mma16816(acc[0][0], av, bv[0], bv[2]);
            mma16816(acc[0][1], av, bv[1], bv[3]);
            if (two) {
                unsigned bv2[4];
                ldsm4(bv2[0], bv2[1], bv2[2], bv2[3],
                      &ksm[(2 * 16 + (lane & 15)) * QSTR + kc]);
                mma16816(acc[1][0], av, bv2[0], bv2[2]);
                mma16816(acc[1][1], av, bv2[1], bv2[3]);
            }
        }
    }

    const size_t Goff = (size_t)(b * NHEADS + h) * HD * HD;
    const int mrow = lane >> 2;
    const int ncol = (lane & 3) * 2;
    const int ntile = two ? 2 : 1;
#pragma unroll
    for (int ti = 0; ti < 2; ++ti) {
        if (ti >= ntile) break;
        int nt = (ti == 0) ? t_nt : 2;
#pragma unroll
        for (int lh = 0; lh < 2; ++lh) {
            int m = t_mt * 16 + mrow;
            int n = nt * 16 + lh * 8 + ncol;
            atomicAdd(&d_G[Goff + m * HD + n],           acc[ti][lh][0]);
            atomicAdd(&d_G[Goff + m * HD + n + 1],       acc[ti][lh][1]);
            atomicAdd(&d_G[Goff + (m + 8) * HD + n],     acc[ti][lh][2]);
            atomicAdd(&d_G[Goff + (m + 8) * HD + n + 1], acc[ti][lh][3]);
        }
    }
#pragma unroll
    for (int s = 0; s < 6; ++s) {
        int ch96 = (tid + s * 256) >> 4;
        atomicAdd(&nrm[ch96], nsq[s]);
    }
    __syncthreads();
    const int gbase = (b * NHEADS + h) * HD;
    if (tid < HD)          atomicAdd(&d_qn[gbase + tid], nrm[tid]);
    else if (tid < 2 * HD) atomicAdd(&d_kn[gbase + tid - HD], nrm[tid]);
}

// ------------------- softmax(attn): one warp per row --------------------------
__global__ void attn_kernel(const float* __restrict__ temp)
{
    const int c    = blockIdx.x;          // 0..47
    const int hb   = blockIdx.y;          // 0..7
    const int b = hb >> 2, h = hb & 3;
    const int lane = threadIdx.x;         // 32
    const int base = (b * NHEADS + h) * HD;

    float qn = fmaxf(sqrtf(d_qn[base + c]), 1e-12f);
    float sc = __ldg(&temp[h]) / qn;

    float kn0 = fmaxf(sqrtf(d_kn[base + lane]), 1e-12f);
    float v0  = d_G[(base + c) * HD + lane] / kn0 * sc;
    float v1  = -1e30f;
    if (lane < 16) {
        float kn1 = fmaxf(sqrtf(d_kn[base + lane + 32]), 1e-12f);
        v1 = d_G[(base + c) * HD + lane + 32] / kn1 * sc;
    }
    float mx = fmaxf(v0, v1);
#pragma unroll
    for (int off = 16; off; off >>= 1)
        mx = fmaxf(mx, __shfl_xor_sync(0xffffffffu, mx, off));
    float e0 = expf(v0 - mx);
    float e1 = (lane < 16) ? expf(v1 - mx) : 0.f;
    float s = e0 + e1;
#pragma unroll
    for (int off = 16; off; off >>= 1)
        s += __shfl_xor_sync(0xffffffffu, s, off);
    float inv = 1.f / s;
    d_attn[(base + c) * HD + lane] = e0 * inv;
    if (lane < 16)
        d_attn[(base + c) * HD + lane + 32] = e1 * inv;
}

// ------------------- M = proj_w @ blockdiag(attn), bf16 out ------------------
__global__ void mmat_kernel(const float* __restrict__ projw)
{
    const int o = blockIdx.x;
    const int b = blockIdx.y;
    const int j = threadIdx.x;       // 0..191
    const int h = j / HD, dd = j % HD;
    const float* aw = d_attn + ((size_t)(b * NHEADS + h) * HD) * HD;
    const float* pw = projw + (size_t)o * CDIM + h * HD;
    float s = 0.f;
#pragma unroll
    for (int c = 0; c < HD; ++c)
        s = fmaf(__ldg(pw + c), aw[c * HD + dd], s);
    d_Mh[((size_t)b * CDIM + o) * CDIM + j] = __float2bfloat16(s);
}

// ----------------------------- launcher --------------------------------------
static constexpr int GEMM0_SMEM  = 192 * 136 * 2 + 2 * 64 * 200 * 2
                                 + (2 * 128 + 2 * 192 + 2 * 128) * 4;     // 107008
static constexpr int GEMM12_SMEM = 192 * 136 * 2 + 2 * 64 * 200 * 2
                                 + (2 * 128 + 2 * 192) * 4;               // 105984
static constexpr int GEMM3_SMEM   = KC3 * BNP3 * 2 + 2 * 64 * KAP3 * 2;   // 104448
static constexpr int GREDUCE_SMEM = 2 * HD * QSTR * 2 + (96 * 9 + 96) * 4; // 54528

extern "C" void kernel_launch(void* const* d_in, const int* in_sizes, int n_in,
                              void* d_out, int out_size)
{
    const float* x        = (const float*)d_in[0];
    const float* ln1_w    = (const float*)d_in[1];
    const float* ln1_b    = (const float*)d_in[2];
    const float* temp     = (const float*)d_in[3];
    const float* qkv_w    = (const float*)d_in[4];
    const float* qkv_dw_w = (const float*)d_in[5];
    const float* proj_w   = (const float*)d_in[6];
    const float* ln2_w    = (const float*)d_in[7];
    const float* ln2_b    = (const float*)d_in[8];
    const float* ffn_in_w = (const float*)d_in[9];
    const float* ffn_dw_w = (const float*)d_in[10];
    const float* ffn_out_w= (const float*)d_in[11];
    float* out = (float*)d_out;

    static bool attr_done = false;
    if (!attr_done) {
        cudaFuncSetAttribute(gemm0_kernel,  cudaFuncAttributeMaxDynamicSharedMemorySize, GEMM0_SMEM);
        cudaFuncSetAttribute(gemm12_kernel, cudaFuncAttributeMaxDynamicSharedMemorySize, GEMM12_SMEM);
        cudaFuncSetAttribute(gemm3_kernel,  cudaFuncAttributeMaxDynamicSharedMemorySize, GEMM3_SMEM);
        cudaFuncSetAttribute(greduce_kernel, cudaFuncAttributeMaxDynamicSharedMemorySize, GREDUCE_SMEM);
        attr_done = true;
    }

    const dim3 blk(256);

    // 1. weight pre-conversion to bf16 (padded) + attention stat zeroing
    prep_w_kernel<<<(FFNCP * CDIM + 255) / 256, blk>>>(qkv_w, ffn_in_w, ffn_out_w);

    // 2. qkv = qkv_w @ LN1(x)   (LN1 stats fused in-block)
    {
        dim3 grid(PIX / 128, BATCH);
        gemm0_kernel<<<grid, blk, GEMM0_SMEM>>>(x, ln1_w, ln1_b);
    }

    // 3. attention statistics (dw3x3 fused; mma; 296 blocks = 2 full waves)
    {
        dim3 grid(37, BATCH * NHEADS);
        greduce_kernel<<<grid, blk, GREDUCE_SMEM>>>(qkv_dw_w);
    }

    // 4. softmax (one warp per attention row)
    {
        dim3 grid(HD, BATCH * NHEADS);
        attn_kernel<<<grid, 32>>>(temp);
    }

    // 5. M = proj_w @ blockdiag(attn)
    {
        dim3 grid(CDIM, BATCH);
        mmat_kernel<<<grid, CDIM>>>(proj_w);
    }

    // 6. fused: x1 = x + M @ dw(V); h = ffn_in_w @ LN2(x1)  (stats stay in smem)
    {
        dim3 grid(PIX / 128, BATCH);
        gemm12_kernel<<<grid, blk, GEMM12_SMEM>>>(qkv_dw_w, ln2_w, ln2_b, x);
    }

    // 7. out = x1 + ffn_out_w @ (gelu(dw(h1)) * dw(h2))  (k-chunked, 2 CTA/SM)
    {
        dim3 grid(PIX / 64, BATCH);
        gemm3_kernel<<<grid, blk, GEMM3_SMEM>>>(ffn_dw_w, out);
    }
}